// round 5
// baseline (speedup 1.0000x reference)
#include <cuda_runtime.h>
#include <cstdint>

#define BB  8
#define CC  512
#define HWD 1024
#define RR  8192   // BB*HWD

// Scratch (device globals — no runtime allocation allowed)
// g_q / g_k hold the projections with the channel dim PERMUTED inside each
// 32-block: pos = (c%4)*8 + c/4 (fragment-vectorized layout for mma.sync).
__device__ float g_q[RR * CC];
__device__ float g_k[RR * CC];
__device__ float g_pmax[RR * BB];   // per-query, per-image max score
__device__ float g_w[BB * HWD];     // softmax gate weights

// ============================================================================
// Helpers
// ============================================================================
__device__ __forceinline__ uint32_t smem_u32(const void* p) {
    uint32_t a;
    asm("{ .reg .u64 t; cvta.to.shared.u64 t, %1; cvt.u32.u64 %0, t; }"
        : "=r"(a) : "l"(p));
    return a;
}
__device__ __forceinline__ void cp_cg16(uint32_t s, const void* g) {
    asm volatile("cp.async.cg.shared.global [%0], [%1], 16;" :: "r"(s), "l"(g));
}
__device__ __forceinline__ void cp_commit() {
    asm volatile("cp.async.commit_group;" ::: "memory");
}
template <int N> __device__ __forceinline__ void cp_wait() {
    asm volatile("cp.async.wait_group %0;" :: "n"(N) : "memory");
}
__device__ __forceinline__ void mma_tf32_16n8k8(
    float* c, uint32_t a0, uint32_t a1, uint32_t a2, uint32_t a3,
    uint32_t b0, uint32_t b1)
{
    asm volatile(
        "mma.sync.aligned.m16n8k8.row.col.f32.tf32.tf32.f32 "
        "{%0,%1,%2,%3}, {%4,%5,%6,%7}, {%8,%9}, {%0,%1,%2,%3};"
        : "+f"(c[0]), "+f"(c[1]), "+f"(c[2]), "+f"(c[3])
        : "r"(a0), "r"(a1), "r"(a2), "r"(a3), "r"(b0), "r"(b1));
}
__device__ __forceinline__ void tf32_split(float v, uint32_t& hi, uint32_t& lo) {
    uint32_t hb = __float_as_uint(v) & 0xFFFFE000u;
    hi = hb;
    lo = __float_as_uint(v - __uint_as_float(hb));
}

// Shared tiling constants (all GEMM kernels: 256 threads, 8 warps)
#define SBK  32      // K-chunk (floats)
#define PADR 36      // pad for [rows][k] tiles (32+4); 16B-aligned rows (144B)
#define PADK 136     // pad for [k][cols] tiles (128+8)

// ============================================================================
// Kernel 1: q/k projection on tf32 mma.sync. grid (64, 4, 2).
//   A = xf tile stored [k][p] (PADK), B = W tile stored [co][k] (PADR).
//   Epilogue writes g_q/g_k with the 32-block channel permutation.
// ============================================================================
#define PJ_A_F (SBK * PADK)          // 4352 floats / stage
#define PJ_B_F (128 * PADR)          // 4608 floats / stage
#define PJ_SMEM (3 * (PJ_A_F + PJ_B_F) * 4)

__global__ __launch_bounds__(256) void proj_tc_kernel(
    const float* __restrict__ x,
    const float* __restrict__ Wq, const float* __restrict__ bq,
    const float* __restrict__ Wk, const float* __restrict__ bk)
{
    extern __shared__ float sm[];
    const uint32_t sbase = smem_u32(sm);

    const int dst = blockIdx.z;
    const float* W    = dst ? Wk : Wq;
    const float* bias = dst ? bk : bq;
    float* out        = dst ? g_k : g_q;

    const int t    = threadIdx.x;
    const int lane = t & 31;
    const int wid  = t >> 5;
    const int wm   = wid >> 2;         // 0..1
    const int wn   = wid & 3;          // 0..3
    const int gid  = lane >> 2;
    const int tig  = lane & 3;

    const int r0  = blockIdx.x * 128;
    const int co0 = blockIdx.y * 128;
    const int b   = r0 / HWD;
    const int p0  = r0 % HWD;
    const float* xb = x + (size_t)b * CC * HWD;

    auto issue = [&](int c) {
        const int s  = c % 3;
        const int k0 = c * SBK;
        uint32_t As = sbase + (uint32_t)(s * PJ_A_F) * 4;
        #pragma unroll
        for (int u = 0; u < 4; u++) {
            int f = t + u * 256, kk = f >> 5, p4 = (f & 31) * 4;
            cp_cg16(As + (uint32_t)(kk * PADK + p4) * 4,
                    xb + (size_t)(k0 + kk) * HWD + p0 + p4);
        }
        uint32_t Bs = sbase + (uint32_t)(3 * PJ_A_F + s * PJ_B_F) * 4;
        #pragma unroll
        for (int u = 0; u < 4; u++) {
            int f = t + u * 256, n = f >> 3, c4 = (f & 7) * 4;
            cp_cg16(Bs + (uint32_t)(n * PADR + c4) * 4,
                    W + (size_t)(co0 + n) * CC + k0 + c4);
        }
        cp_commit();
    };

    float acc[4][4][4];
    #pragma unroll
    for (int mt = 0; mt < 4; mt++)
        #pragma unroll
        for (int nt = 0; nt < 4; nt++)
            #pragma unroll
            for (int v = 0; v < 4; v++) acc[mt][nt][v] = 0.f;

    issue(0); issue(1);
    for (int c = 0; c < 16; ++c) {
        if (c < 15) cp_wait<1>(); else cp_wait<0>();
        __syncthreads();
        if (c + 2 < 16) issue(c + 2);

        const float* Ab = sm + (c % 3) * PJ_A_F;                 // [k][p]
        const float* Bb = sm + 3 * PJ_A_F + (c % 3) * PJ_B_F;    // [co][k]

        #pragma unroll
        for (int ks = 0; ks < 4; ++ks) {
            const int col = ks * 8 + tig;
            uint32_t a[4][4];
            #pragma unroll
            for (int mt = 0; mt < 4; ++mt) {
                int r = wm * 64 + mt * 16 + gid;
                a[mt][0] = __float_as_uint(Ab[col * PADK + r]);
                a[mt][1] = __float_as_uint(Ab[col * PADK + r + 8]);
                a[mt][2] = __float_as_uint(Ab[(col + 4) * PADK + r]);
                a[mt][3] = __float_as_uint(Ab[(col + 4) * PADK + r + 8]);
            }
            #pragma unroll
            for (int nt = 0; nt < 4; ++nt) {
                int n = wn * 32 + nt * 8 + gid;
                uint32_t b0 = __float_as_uint(Bb[n * PADR + col]);
                uint32_t b1 = __float_as_uint(Bb[n * PADR + col + 4]);
                #pragma unroll
                for (int mt = 0; mt < 4; ++mt)
                    mma_tf32_16n8k8(acc[mt][nt],
                                    a[mt][0], a[mt][1], a[mt][2], a[mt][3],
                                    b0, b1);
            }
        }
    }

    // Epilogue: permuted write. c = within-32 column, pos = (c%4)*8 + c/4.
    #pragma unroll
    for (int mt = 0; mt < 4; ++mt) {
        int row = r0 + wm * 64 + mt * 16 + gid;
        #pragma unroll
        for (int nt = 0; nt < 4; ++nt) {
            int cbase = co0 + wn * 32;           // 32-aligned block base
            int c0 = nt * 8 + tig * 2;           // even, in [0,32)
            int c1 = c0 + 1;
            int pp0 = ((c0 & 3) << 3) | (c0 >> 2);
            int pp1 = ((c1 & 3) << 3) | (c1 >> 2);
            float bs0 = bias[cbase + c0], bs1 = bias[cbase + c1];
            out[(size_t)row * CC + cbase + pp0]       = acc[mt][nt][0] + bs0;
            out[(size_t)row * CC + cbase + pp1]       = acc[mt][nt][1] + bs1;
            out[(size_t)(row + 8) * CC + cbase + pp0] = acc[mt][nt][2] + bs0;
            out[(size_t)(row + 8) * CC + cbase + pp1] = acc[mt][nt][3] + bs1;
        }
    }
}

// ============================================================================
// Kernel 2: fused scores + per-image max via tf32 mma. grid (64, 8).
//   g_q/g_k are channel-permuted -> fragment loads are LDS.128:
//   per 32-K chunk each thread does 32 vector loads + issues 128 mma/warp.
// ============================================================================
#define SNT   256
#define SC_A_F (128 * PADR)          // 4608
#define SC_B_F (SNT * PADR)          // 9216
#define SC_RED (3 * (SC_A_F + SC_B_F))
#define SC_SMEM ((SC_RED + 512) * 4)

__global__ __launch_bounds__(256, 1) void scores_mma_kernel()
{
    extern __shared__ float sm[];
    const uint32_t sbase = smem_u32(sm);

    const int t    = threadIdx.x;
    const int lane = t & 31;
    const int wid  = t >> 5;
    const int wm   = wid >> 2;
    const int wn   = wid & 3;
    const int gid  = lane >> 2;
    const int tig  = lane & 3;
    const int q0   = blockIdx.x * 128;
    const size_t kb = (size_t)blockIdx.y * HWD;

    float* red = sm + SC_RED;
    float qm = -1e30f;
    const float* qp = g_q + (size_t)q0 * CC;

    auto issue = [&](int g) {
        const int s   = g % 3;
        const int ntl = g >> 4;
        const int k0  = (g & 15) * SBK;
        uint32_t As = sbase + (uint32_t)(s * SC_A_F) * 4;
        #pragma unroll
        for (int u = 0; u < 4; u++) {
            int f = t + u * 256, r = f >> 3, c4 = (f & 7) * 4;
            cp_cg16(As + (uint32_t)(r * PADR + c4) * 4,
                    qp + (size_t)r * CC + k0 + c4);
        }
        uint32_t Bs = sbase + (uint32_t)(3 * SC_A_F + s * SC_B_F) * 4;
        const float* kp = g_k + (kb + (size_t)ntl * SNT) * CC;
        #pragma unroll
        for (int u = 0; u < 8; u++) {
            int f = t + u * 256, n = f >> 3, c4 = (f & 7) * 4;
            cp_cg16(Bs + (uint32_t)(n * PADR + c4) * 4,
                    kp + (size_t)n * CC + k0 + c4);
        }
        cp_commit();
    };

    float acc[4][8][4];

    issue(0); issue(1);
    for (int g = 0; g < 64; ++g) {
        if ((g & 15) == 0) {
            #pragma unroll
            for (int mt = 0; mt < 4; mt++)
                #pragma unroll
                for (int nt = 0; nt < 8; nt++)
                    #pragma unroll
                    for (int v = 0; v < 4; v++) acc[mt][nt][v] = 0.f;
        }
        if (g < 63) cp_wait<1>(); else cp_wait<0>();
        __syncthreads();
        if (g + 2 < 64) issue(g + 2);

        const float* Ab = sm + (g % 3) * SC_A_F;                 // [r][kperm]
        const float* Bb = sm + 3 * SC_A_F + (g % 3) * SC_B_F;    // [n][kperm]

        // ks-halves: float4 at [row][tig*8 + ksh*4] covers ks = 2ksh, 2ksh+1
        #pragma unroll
        for (int ksh = 0; ksh < 2; ++ksh) {
            const int fo = tig * 8 + ksh * 4;
            float4 bw[8];
            #pragma unroll
            for (int nt = 0; nt < 8; ++nt) {
                int n = wn * 64 + nt * 8 + gid;
                bw[nt] = *(const float4*)&Bb[n * PADR + fo];
            }
            #pragma unroll
            for (int mt = 0; mt < 4; ++mt) {
                int r = wm * 64 + mt * 16 + gid;
                float4 va = *(const float4*)&Ab[r * PADR + fo];
                float4 vb = *(const float4*)&Ab[(r + 8) * PADR + fo];
                #pragma unroll
                for (int nt = 0; nt < 8; ++nt) {
                    mma_tf32_16n8k8(acc[mt][nt],
                                    __float_as_uint(va.x), __float_as_uint(vb.x),
                                    __float_as_uint(va.y), __float_as_uint(vb.y),
                                    __float_as_uint(bw[nt].x), __float_as_uint(bw[nt].y));
                    mma_tf32_16n8k8(acc[mt][nt],
                                    __float_as_uint(va.z), __float_as_uint(vb.z),
                                    __float_as_uint(va.w), __float_as_uint(vb.w),
                                    __float_as_uint(bw[nt].z), __float_as_uint(bw[nt].w));
                }
            }
        }

        if ((g & 15) == 15) {
            #pragma unroll
            for (int mt = 0; mt < 4; ++mt) {
                float m0 = -1e30f, m1 = -1e30f;
                #pragma unroll
                for (int nt = 0; nt < 8; ++nt) {
                    m0 = fmaxf(m0, fmaxf(acc[mt][nt][0], acc[mt][nt][1]));
                    m1 = fmaxf(m1, fmaxf(acc[mt][nt][2], acc[mt][nt][3]));
                }
                m0 = fmaxf(m0, __shfl_xor_sync(0xffffffffu, m0, 1));
                m0 = fmaxf(m0, __shfl_xor_sync(0xffffffffu, m0, 2));
                m1 = fmaxf(m1, __shfl_xor_sync(0xffffffffu, m1, 1));
                m1 = fmaxf(m1, __shfl_xor_sync(0xffffffffu, m1, 2));
                if (tig == 0) {
                    int r = wm * 64 + mt * 16 + gid;
                    red[wn * 128 + r]     = m0;
                    red[wn * 128 + r + 8] = m1;
                }
            }
            __syncthreads();
            if (t < 128) {
                float v = fmaxf(fmaxf(red[t], red[128 + t]),
                                fmaxf(red[256 + t], red[384 + t]));
                qm = fmaxf(qm, v);
            }
            __syncthreads();
        }
    }

    if (t < 128)
        g_pmax[(size_t)(q0 + t) * BB + blockIdx.y] = qm;
}

// ============================================================================
// Kernel 3: logits = mean-over-images(pmax) / sqrt(C); softmax per batch.
// ============================================================================
__global__ __launch_bounds__(256) void softmax_kernel()
{
    const int b = blockIdx.x;
    const int t = threadIdx.x;
    __shared__ float smr[256];
    __shared__ float logits[HWD];
    const float scale = 1.0f / sqrtf((float)CC);

    float lmax = -1e30f;
    for (int p = t; p < HWD; p += 256) {
        float s = 0.f;
        #pragma unroll
        for (int img = 0; img < BB; img++)
            s += g_pmax[(size_t)(b * HWD + p) * BB + img];
        float lg = s * (1.0f / BB) * scale;
        logits[p] = lg;
        lmax = fmaxf(lmax, lg);
    }
    smr[t] = lmax; __syncthreads();
    for (int s = 128; s > 0; s >>= 1) {
        if (t < s) smr[t] = fmaxf(smr[t], smr[t + s]);
        __syncthreads();
    }
    float gmax = smr[0]; __syncthreads();

    float lsum = 0.f;
    for (int p = t; p < HWD; p += 256) {
        float e = expf(logits[p] - gmax);
        logits[p] = e;
        lsum += e;
    }
    smr[t] = lsum; __syncthreads();
    for (int s = 128; s > 0; s >>= 1) {
        if (t < s) smr[t] += smr[t + s];
        __syncthreads();
    }
    float inv = 1.0f / smr[0];
    for (int p = t; p < HWD; p += 256)
        g_w[b * HWD + p] = logits[p] * inv;
}

// ============================================================================
// Kernel 4: gated output conv on 3xTF32 split mma. grid (4, 8, 8).
// ============================================================================
__global__ __launch_bounds__(256) void outconv_tc_kernel(
    const float* __restrict__ x, const float* __restrict__ W6,
    const float* __restrict__ b6, float* __restrict__ out)
{
    extern __shared__ float sm[];
    const uint32_t sbase = smem_u32(sm);

    const int t    = threadIdx.x;
    const int lane = t & 31;
    const int wid  = t >> 5;
    const int wm   = wid >> 2;
    const int wn   = wid & 3;
    const int gid  = lane >> 2;
    const int tig  = lane & 3;

    const int co0 = blockIdx.x * 128;
    const int p0  = blockIdx.y * 128;
    const int b   = blockIdx.z;
    const float* xb = x + (size_t)b * CC * HWD;

    auto issue = [&](int c) {
        const int s  = c % 3;
        const int k0 = c * SBK;
        uint32_t As = sbase + (uint32_t)(s * PJ_B_F) * 4;      // [co][k] PADR
        #pragma unroll
        for (int u = 0; u < 4; u++) {
            int f = t + u * 256, m = f >> 3, c4 = (f & 7) * 4;
            cp_cg16(As + (uint32_t)(m * PADR + c4) * 4,
                    W6 + (size_t)(co0 + m) * CC + k0 + c4);
        }
        uint32_t Bs = sbase + (uint32_t)(3 * PJ_B_F + s * PJ_A_F) * 4;  // [k][p] PADK
        #pragma unroll
        for (int u = 0; u < 4; u++) {
            int f = t + u * 256, kk = f >> 5, p4 = (f & 31) * 4;
            cp_cg16(Bs + (uint32_t)(kk * PADK + p4) * 4,
                    xb + (size_t)(k0 + kk) * HWD + p0 + p4);
        }
        cp_commit();
    };

    float acc[4][4][4];
    #pragma unroll
    for (int mt = 0; mt < 4; mt++)
        #pragma unroll
        for (int nt = 0; nt < 4; nt++)
            #pragma unroll
            for (int v = 0; v < 4; v++) acc[mt][nt][v] = 0.f;

    issue(0); issue(1);
    for (int c = 0; c < 16; ++c) {
        if (c < 15) cp_wait<1>(); else cp_wait<0>();
        __syncthreads();
        if (c + 2 < 16) issue(c + 2);

        const float* Ab = sm + (c % 3) * PJ_B_F;                 // [co][k]
        const float* Bb = sm + 3 * PJ_B_F + (c % 3) * PJ_A_F;    // [k][p]

        #pragma unroll
        for (int ks = 0; ks < 4; ++ks) {
            const int col = ks * 8 + tig;
            uint32_t ah[4][4], al[4][4];
            #pragma unroll
            for (int mt = 0; mt < 4; ++mt) {
                int m = wm * 64 + mt * 16 + gid;
                tf32_split(Ab[m * PADR + col],           ah[mt][0], al[mt][0]);
                tf32_split(Ab[(m + 8) * PADR + col],     ah[mt][1], al[mt][1]);
                tf32_split(Ab[m * PADR + col + 4],       ah[mt][2], al[mt][2]);
                tf32_split(Ab[(m + 8) * PADR + col + 4], ah[mt][3], al[mt][3]);
            }
            #pragma unroll
            for (int nt = 0; nt < 4; ++nt) {
                int n = wn * 32 + nt * 8 + gid;
                uint32_t bh0, bl0, bh1, bl1;
                tf32_split(Bb[col * PADK + n],       bh0, bl0);
                tf32_split(Bb[(col + 4) * PADK + n], bh1, bl1);
                #pragma unroll
                for (int mt = 0; mt < 4; ++mt) {
                    mma_tf32_16n8k8(acc[mt][nt],
                                    ah[mt][0], ah[mt][1], ah[mt][2], ah[mt][3],
                                    bh0, bh1);
                    mma_tf32_16n8k8(acc[mt][nt],
                                    ah[mt][0], ah[mt][1], ah[mt][2], ah[mt][3],
                                    bl0, bl1);
                    mma_tf32_16n8k8(acc[mt][nt],
                                    al[mt][0], al[mt][1], al[mt][2], al[mt][3],
                                    bh0, bh1);
                }
            }
        }
    }

    #pragma unroll
    for (int mt = 0; mt < 4; ++mt) {
        int co = co0 + wm * 64 + mt * 16 + gid;
        float bs0 = b6[co], bs1 = b6[co + 8];
        #pragma unroll
        for (int nt = 0; nt < 4; ++nt) {
            int p = p0 + wn * 32 + nt * 8 + tig * 2;
            float g0 = g_w[b * HWD + p];
            float g1 = g_w[b * HWD + p + 1];
            float2 o0 = { acc[mt][nt][0] * g0 + bs0, acc[mt][nt][1] * g1 + bs0 };
            float2 o1 = { acc[mt][nt][2] * g0 + bs1, acc[mt][nt][3] * g1 + bs1 };
            *(float2*)&out[((size_t)(b * CC + co)) * HWD + p]     = o0;
            *(float2*)&out[((size_t)(b * CC + co + 8)) * HWD + p] = o1;
        }
    }
}

// ============================================================================
extern "C" void kernel_launch(void* const* d_in, const int* in_sizes, int n_in,
                              void* d_out, int out_size)
{
    const float* x  = (const float*)d_in[0];
    const float* Wq = (const float*)d_in[1];
    const float* bq = (const float*)d_in[2];
    const float* Wk = (const float*)d_in[3];
    const float* bk = (const float*)d_in[4];
    const float* W6 = (const float*)d_in[5];
    const float* b6 = (const float*)d_in[6];
    float* out = (float*)d_out;

    cudaFuncSetAttribute(proj_tc_kernel,
                         cudaFuncAttributeMaxDynamicSharedMemorySize, PJ_SMEM);
    cudaFuncSetAttribute(scores_mma_kernel,
                         cudaFuncAttributeMaxDynamicSharedMemorySize, SC_SMEM);
    cudaFuncSetAttribute(outconv_tc_kernel,
                         cudaFuncAttributeMaxDynamicSharedMemorySize, PJ_SMEM);

    dim3 blk(256);
    proj_tc_kernel<<<dim3(RR / 128, CC / 128, 2), blk, PJ_SMEM>>>(x, Wq, bq, Wk, bk);
    scores_mma_kernel<<<dim3(RR / 128, BB), blk, SC_SMEM>>>();
    softmax_kernel<<<BB, blk>>>();
    outconv_tc_kernel<<<dim3(CC / 128, HWD / 128, BB), blk, PJ_SMEM>>>(x, W6, b6, out);
}

// round 6
// speedup vs baseline: 1.0780x; 1.0780x over previous
#include <cuda_runtime.h>
#include <cstdint>

#define BB  8
#define CC  512
#define HWD 1024
#define RR  8192   // BB*HWD

// Scratch (device globals — no runtime allocation allowed)
__device__ float g_q[RR * CC];
__device__ float g_k[RR * CC];
__device__ float g_pmax[RR * BB];   // per-query, per-image max score
__device__ float g_w[BB * HWD];     // softmax gate weights

// ============================================================================
// Helpers
// ============================================================================
__device__ __forceinline__ uint32_t smem_u32(const void* p) {
    uint32_t a;
    asm("{ .reg .u64 t; cvta.to.shared.u64 t, %1; cvt.u32.u64 %0, t; }"
        : "=r"(a) : "l"(p));
    return a;
}
__device__ __forceinline__ void cp_cg16(uint32_t s, const void* g) {
    asm volatile("cp.async.cg.shared.global [%0], [%1], 16;" :: "r"(s), "l"(g));
}
__device__ __forceinline__ void cp_commit() {
    asm volatile("cp.async.commit_group;" ::: "memory");
}
template <int N> __device__ __forceinline__ void cp_wait() {
    asm volatile("cp.async.wait_group %0;" :: "n"(N) : "memory");
}
__device__ __forceinline__ void mma_tf32_16n8k8(
    float* c, uint32_t a0, uint32_t a1, uint32_t a2, uint32_t a3,
    uint32_t b0, uint32_t b1)
{
    asm volatile(
        "mma.sync.aligned.m16n8k8.row.col.f32.tf32.tf32.f32 "
        "{%0,%1,%2,%3}, {%4,%5,%6,%7}, {%8,%9}, {%0,%1,%2,%3};"
        : "+f"(c[0]), "+f"(c[1]), "+f"(c[2]), "+f"(c[3])
        : "r"(a0), "r"(a1), "r"(a2), "r"(a3), "r"(b0), "r"(b1));
}
__device__ __forceinline__ void tf32_split(float v, uint32_t& hi, uint32_t& lo) {
    uint32_t hb = __float_as_uint(v) & 0xFFFFE000u;
    hi = hb;
    lo = __float_as_uint(v - __uint_as_float(hb));
}

// Shared tiling constants (all GEMM kernels: 256 threads, 8 warps)
#define SBK  32      // K-chunk (floats)
#define PADR 36      // pad for [rows][k] tiles (32+4); 16B-aligned rows
#define PADK 136     // pad for [k][cols] tiles (128+8)

// ============================================================================
// Kernel 1: q/k projection on tf32 mma.sync. grid (64, 4, 2). 2 CTAs/SM.
//   A = xf tile stored [k][p] (PADK), B = W tile stored [co][k] (PADR).
// ============================================================================
#define PJ_A_F (SBK * PADK)          // 4352 floats / stage
#define PJ_B_F (128 * PADR)          // 4608 floats / stage
#define PJ_SMEM (3 * (PJ_A_F + PJ_B_F) * 4)

__global__ __launch_bounds__(256, 2) void proj_tc_kernel(
    const float* __restrict__ x,
    const float* __restrict__ Wq, const float* __restrict__ bq,
    const float* __restrict__ Wk, const float* __restrict__ bk)
{
    extern __shared__ float sm[];
    const uint32_t sbase = smem_u32(sm);

    const int dst = blockIdx.z;
    const float* W    = dst ? Wk : Wq;
    const float* bias = dst ? bk : bq;
    float* out        = dst ? g_k : g_q;

    const int t    = threadIdx.x;
    const int lane = t & 31;
    const int wid  = t >> 5;
    const int wm   = wid >> 2;         // 0..1
    const int wn   = wid & 3;          // 0..3
    const int gid  = lane >> 2;
    const int tig  = lane & 3;

    const int r0  = blockIdx.x * 128;
    const int co0 = blockIdx.y * 128;
    const int b   = r0 / HWD;
    const int p0  = r0 % HWD;
    const float* xb = x + (size_t)b * CC * HWD;

    auto issue = [&](int c) {
        const int s  = c % 3;
        const int k0 = c * SBK;
        uint32_t As = sbase + (uint32_t)(s * PJ_A_F) * 4;
        #pragma unroll
        for (int u = 0; u < 4; u++) {
            int f = t + u * 256, kk = f >> 5, p4 = (f & 31) * 4;
            cp_cg16(As + (uint32_t)(kk * PADK + p4) * 4,
                    xb + (size_t)(k0 + kk) * HWD + p0 + p4);
        }
        uint32_t Bs = sbase + (uint32_t)(3 * PJ_A_F + s * PJ_B_F) * 4;
        #pragma unroll
        for (int u = 0; u < 4; u++) {
            int f = t + u * 256, n = f >> 3, c4 = (f & 7) * 4;
            cp_cg16(Bs + (uint32_t)(n * PADR + c4) * 4,
                    W + (size_t)(co0 + n) * CC + k0 + c4);
        }
        cp_commit();
    };

    float acc[4][4][4];
    #pragma unroll
    for (int mt = 0; mt < 4; mt++)
        #pragma unroll
        for (int nt = 0; nt < 4; nt++)
            #pragma unroll
            for (int v = 0; v < 4; v++) acc[mt][nt][v] = 0.f;

    issue(0); issue(1);
    for (int c = 0; c < 16; ++c) {
        if (c < 15) cp_wait<1>(); else cp_wait<0>();
        __syncthreads();
        if (c + 2 < 16) issue(c + 2);

        const float* Ab = sm + (c % 3) * PJ_A_F;                 // [k][p]
        const float* Bb = sm + 3 * PJ_A_F + (c % 3) * PJ_B_F;    // [co][k]

        #pragma unroll
        for (int ks = 0; ks < 4; ++ks) {
            const int col = ks * 8 + tig;
            uint32_t a[4][4];
            #pragma unroll
            for (int mt = 0; mt < 4; ++mt) {
                int r = wm * 64 + mt * 16 + gid;
                a[mt][0] = __float_as_uint(Ab[col * PADK + r]);
                a[mt][1] = __float_as_uint(Ab[col * PADK + r + 8]);
                a[mt][2] = __float_as_uint(Ab[(col + 4) * PADK + r]);
                a[mt][3] = __float_as_uint(Ab[(col + 4) * PADK + r + 8]);
            }
            #pragma unroll
            for (int nt = 0; nt < 4; ++nt) {
                int n = wn * 32 + nt * 8 + gid;
                uint32_t b0 = __float_as_uint(Bb[n * PADR + col]);
                uint32_t b1 = __float_as_uint(Bb[n * PADR + col + 4]);
                #pragma unroll
                for (int mt = 0; mt < 4; ++mt)
                    mma_tf32_16n8k8(acc[mt][nt],
                                    a[mt][0], a[mt][1], a[mt][2], a[mt][3],
                                    b0, b1);
            }
        }
    }

    #pragma unroll
    for (int mt = 0; mt < 4; ++mt) {
        int row = r0 + wm * 64 + mt * 16 + gid;
        #pragma unroll
        for (int nt = 0; nt < 4; ++nt) {
            int co = co0 + wn * 32 + nt * 8 + tig * 2;
            float bs0 = bias[co], bs1 = bias[co + 1];
            float2 o0 = { acc[mt][nt][0] + bs0, acc[mt][nt][1] + bs1 };
            float2 o1 = { acc[mt][nt][2] + bs0, acc[mt][nt][3] + bs1 };
            *(float2*)&out[(size_t)row * CC + co]       = o0;
            *(float2*)&out[(size_t)(row + 8) * CC + co] = o1;
        }
    }
}

// ============================================================================
// Kernel 2: fused scores + per-image max via tf32 mma. grid (64, 8).
//   Block: 128 queries x 1024 keys (one image), N-tile = 128 keys
//   (8 N-tiles x 16 K-chunks = 128 chunks), 3-stage cp.async ring.
//   acc = 64 regs/thread -> 2 CTAs/SM (128-reg cap, 110KB smem each).
// ============================================================================
#define SNT   128
#define SC_A_F (128 * PADR)          // 4608
#define SC_B_F (SNT * PADR)          // 4608
#define SC_RED (3 * (SC_A_F + SC_B_F))
#define SC_SMEM ((SC_RED + 512) * 4)

__global__ __launch_bounds__(256, 2) void scores_mma_kernel()
{
    extern __shared__ float sm[];
    const uint32_t sbase = smem_u32(sm);

    const int t    = threadIdx.x;
    const int lane = t & 31;
    const int wid  = t >> 5;
    const int wm   = wid >> 2;
    const int wn   = wid & 3;
    const int gid  = lane >> 2;
    const int tig  = lane & 3;
    const int q0   = blockIdx.x * 128;
    const size_t kb = (size_t)blockIdx.y * HWD;

    float* red = sm + SC_RED;
    float qm = -1e30f;
    const float* qp = g_q + (size_t)q0 * CC;

    auto issue = [&](int g) {
        const int s   = g % 3;
        const int ntl = g >> 4;
        const int k0  = (g & 15) * SBK;
        uint32_t As = sbase + (uint32_t)(s * SC_A_F) * 4;
        #pragma unroll
        for (int u = 0; u < 4; u++) {
            int f = t + u * 256, r = f >> 3, c4 = (f & 7) * 4;
            cp_cg16(As + (uint32_t)(r * PADR + c4) * 4,
                    qp + (size_t)r * CC + k0 + c4);
        }
        uint32_t Bs = sbase + (uint32_t)(3 * SC_A_F + s * SC_B_F) * 4;
        const float* kp = g_k + (kb + (size_t)ntl * SNT) * CC;
        #pragma unroll
        for (int u = 0; u < 4; u++) {
            int f = t + u * 256, n = f >> 3, c4 = (f & 7) * 4;
            cp_cg16(Bs + (uint32_t)(n * PADR + c4) * 4,
                    kp + (size_t)n * CC + k0 + c4);
        }
        cp_commit();
    };

    float acc[4][4][4];

    issue(0); issue(1);
    for (int g = 0; g < 128; ++g) {
        if ((g & 15) == 0) {
            #pragma unroll
            for (int mt = 0; mt < 4; mt++)
                #pragma unroll
                for (int nt = 0; nt < 4; nt++)
                    #pragma unroll
                    for (int v = 0; v < 4; v++) acc[mt][nt][v] = 0.f;
        }
        if (g < 127) cp_wait<1>(); else cp_wait<0>();
        __syncthreads();
        if (g + 2 < 128) issue(g + 2);

        const float* Ab = sm + (g % 3) * SC_A_F;                 // [r][k]
        const float* Bb = sm + 3 * SC_A_F + (g % 3) * SC_B_F;    // [n][k]

        #pragma unroll
        for (int ks = 0; ks < 4; ++ks) {
            const int col = ks * 8 + tig;
            uint32_t a[4][4];
            #pragma unroll
            for (int mt = 0; mt < 4; ++mt) {
                int r = wm * 64 + mt * 16 + gid;
                a[mt][0] = __float_as_uint(Ab[r * PADR + col]);
                a[mt][1] = __float_as_uint(Ab[(r + 8) * PADR + col]);
                a[mt][2] = __float_as_uint(Ab[r * PADR + col + 4]);
                a[mt][3] = __float_as_uint(Ab[(r + 8) * PADR + col + 4]);
            }
            #pragma unroll
            for (int nt = 0; nt < 4; ++nt) {
                int n = wn * 32 + nt * 8 + gid;
                uint32_t b0 = __float_as_uint(Bb[n * PADR + col]);
                uint32_t b1 = __float_as_uint(Bb[n * PADR + col + 4]);
                #pragma unroll
                for (int mt = 0; mt < 4; ++mt)
                    mma_tf32_16n8k8(acc[mt][nt],
                                    a[mt][0], a[mt][1], a[mt][2], a[mt][3],
                                    b0, b1);
            }
        }

        if ((g & 15) == 15) {
            #pragma unroll
            for (int mt = 0; mt < 4; ++mt) {
                float m0 = -1e30f, m1 = -1e30f;
                #pragma unroll
                for (int nt = 0; nt < 4; ++nt) {
                    m0 = fmaxf(m0, fmaxf(acc[mt][nt][0], acc[mt][nt][1]));
                    m1 = fmaxf(m1, fmaxf(acc[mt][nt][2], acc[mt][nt][3]));
                }
                m0 = fmaxf(m0, __shfl_xor_sync(0xffffffffu, m0, 1));
                m0 = fmaxf(m0, __shfl_xor_sync(0xffffffffu, m0, 2));
                m1 = fmaxf(m1, __shfl_xor_sync(0xffffffffu, m1, 1));
                m1 = fmaxf(m1, __shfl_xor_sync(0xffffffffu, m1, 2));
                if (tig == 0) {
                    int r = wm * 64 + mt * 16 + gid;
                    red[wn * 128 + r]     = m0;
                    red[wn * 128 + r + 8] = m1;
                }
            }
            __syncthreads();
            if (t < 128) {
                float v = fmaxf(fmaxf(red[t], red[128 + t]),
                                fmaxf(red[256 + t], red[384 + t]));
                qm = fmaxf(qm, v);
            }
            __syncthreads();
        }
    }

    if (t < 128)
        g_pmax[(size_t)(q0 + t) * BB + blockIdx.y] = qm;
}

// ============================================================================
// Kernel 3: logits = mean-over-images(pmax) / sqrt(C); softmax per batch.
// ============================================================================
__global__ __launch_bounds__(256) void softmax_kernel()
{
    const int b = blockIdx.x;
    const int t = threadIdx.x;
    __shared__ float smr[256];
    __shared__ float logits[HWD];
    const float scale = 1.0f / sqrtf((float)CC);

    float lmax = -1e30f;
    for (int p = t; p < HWD; p += 256) {
        float s = 0.f;
        #pragma unroll
        for (int img = 0; img < BB; img++)
            s += g_pmax[(size_t)(b * HWD + p) * BB + img];
        float lg = s * (1.0f / BB) * scale;
        logits[p] = lg;
        lmax = fmaxf(lmax, lg);
    }
    smr[t] = lmax; __syncthreads();
    for (int s = 128; s > 0; s >>= 1) {
        if (t < s) smr[t] = fmaxf(smr[t], smr[t + s]);
        __syncthreads();
    }
    float gmax = smr[0]; __syncthreads();

    float lsum = 0.f;
    for (int p = t; p < HWD; p += 256) {
        float e = expf(logits[p] - gmax);
        logits[p] = e;
        lsum += e;
    }
    smr[t] = lsum; __syncthreads();
    for (int s = 128; s > 0; s >>= 1) {
        if (t < s) smr[t] += smr[t + s];
        __syncthreads();
    }
    float inv = 1.0f / smr[0];
    for (int p = t; p < HWD; p += 256)
        g_w[b * HWD + p] = logits[p] * inv;
}

// ============================================================================
// Kernel 4: gated output conv on 3xTF32 split mma. grid (4, 8, 8). 2 CTAs/SM.
// ============================================================================
__global__ __launch_bounds__(256, 2) void outconv_tc_kernel(
    const float* __restrict__ x, const float* __restrict__ W6,
    const float* __restrict__ b6, float* __restrict__ out)
{
    extern __shared__ float sm[];
    const uint32_t sbase = smem_u32(sm);

    const int t    = threadIdx.x;
    const int lane = t & 31;
    const int wid  = t >> 5;
    const int wm   = wid >> 2;
    const int wn   = wid & 3;
    const int gid  = lane >> 2;
    const int tig  = lane & 3;

    const int co0 = blockIdx.x * 128;
    const int p0  = blockIdx.y * 128;
    const int b   = blockIdx.z;
    const float* xb = x + (size_t)b * CC * HWD;

    auto issue = [&](int c) {
        const int s  = c % 3;
        const int k0 = c * SBK;
        uint32_t As = sbase + (uint32_t)(s * PJ_B_F) * 4;      // [co][k] PADR
        #pragma unroll
        for (int u = 0; u < 4; u++) {
            int f = t + u * 256, m = f >> 3, c4 = (f & 7) * 4;
            cp_cg16(As + (uint32_t)(m * PADR + c4) * 4,
                    W6 + (size_t)(co0 + m) * CC + k0 + c4);
        }
        uint32_t Bs = sbase + (uint32_t)(3 * PJ_B_F + s * PJ_A_F) * 4;  // [k][p] PADK
        #pragma unroll
        for (int u = 0; u < 4; u++) {
            int f = t + u * 256, kk = f >> 5, p4 = (f & 31) * 4;
            cp_cg16(Bs + (uint32_t)(kk * PADK + p4) * 4,
                    xb + (size_t)(k0 + kk) * HWD + p0 + p4);
        }
        cp_commit();
    };

    float acc[4][4][4];
    #pragma unroll
    for (int mt = 0; mt < 4; mt++)
        #pragma unroll
        for (int nt = 0; nt < 4; nt++)
            #pragma unroll
            for (int v = 0; v < 4; v++) acc[mt][nt][v] = 0.f;

    issue(0); issue(1);
    for (int c = 0; c < 16; ++c) {
        if (c < 15) cp_wait<1>(); else cp_wait<0>();
        __syncthreads();
        if (c + 2 < 16) issue(c + 2);

        const float* Ab = sm + (c % 3) * PJ_B_F;                 // [co][k]
        const float* Bb = sm + 3 * PJ_B_F + (c % 3) * PJ_A_F;    // [k][p]

        #pragma unroll
        for (int ks = 0; ks < 4; ++ks) {
            const int col = ks * 8 + tig;
            uint32_t ah[4][4], al[4][4];
            #pragma unroll
            for (int mt = 0; mt < 4; ++mt) {
                int m = wm * 64 + mt * 16 + gid;
                tf32_split(Ab[m * PADR + col],           ah[mt][0], al[mt][0]);
                tf32_split(Ab[(m + 8) * PADR + col],     ah[mt][1], al[mt][1]);
                tf32_split(Ab[m * PADR + col + 4],       ah[mt][2], al[mt][2]);
                tf32_split(Ab[(m + 8) * PADR + col + 4], ah[mt][3], al[mt][3]);
            }
            #pragma unroll
            for (int nt = 0; nt < 4; ++nt) {
                int n = wn * 32 + nt * 8 + gid;
                uint32_t bh0, bl0, bh1, bl1;
                tf32_split(Bb[col * PADK + n],       bh0, bl0);
                tf32_split(Bb[(col + 4) * PADK + n], bh1, bl1);
                #pragma unroll
                for (int mt = 0; mt < 4; ++mt) {
                    mma_tf32_16n8k8(acc[mt][nt],
                                    ah[mt][0], ah[mt][1], ah[mt][2], ah[mt][3],
                                    bh0, bh1);
                    mma_tf32_16n8k8(acc[mt][nt],
                                    ah[mt][0], ah[mt][1], ah[mt][2], ah[mt][3],
                                    bl0, bl1);
                    mma_tf32_16n8k8(acc[mt][nt],
                                    al[mt][0], al[mt][1], al[mt][2], al[mt][3],
                                    bh0, bh1);
                }
            }
        }
    }

    #pragma unroll
    for (int mt = 0; mt < 4; ++mt) {
        int co = co0 + wm * 64 + mt * 16 + gid;
        float bs0 = b6[co], bs1 = b6[co + 8];
        #pragma unroll
        for (int nt = 0; nt < 4; ++nt) {
            int p = p0 + wn * 32 + nt * 8 + tig * 2;
            float g0 = g_w[b * HWD + p];
            float g1 = g_w[b * HWD + p + 1];
            float2 o0 = { acc[mt][nt][0] * g0 + bs0, acc[mt][nt][1] * g1 + bs0 };
            float2 o1 = { acc[mt][nt][2] * g0 + bs1, acc[mt][nt][3] * g1 + bs1 };
            *(float2*)&out[((size_t)(b * CC + co)) * HWD + p]     = o0;
            *(float2*)&out[((size_t)(b * CC + co + 8)) * HWD + p] = o1;
        }
    }
}

// ============================================================================
extern "C" void kernel_launch(void* const* d_in, const int* in_sizes, int n_in,
                              void* d_out, int out_size)
{
    const float* x  = (const float*)d_in[0];
    const float* Wq = (const float*)d_in[1];
    const float* bq = (const float*)d_in[2];
    const float* Wk = (const float*)d_in[3];
    const float* bk = (const float*)d_in[4];
    const float* W6 = (const float*)d_in[5];
    const float* b6 = (const float*)d_in[6];
    float* out = (float*)d_out;

    cudaFuncSetAttribute(proj_tc_kernel,
                         cudaFuncAttributeMaxDynamicSharedMemorySize, PJ_SMEM);
    cudaFuncSetAttribute(scores_mma_kernel,
                         cudaFuncAttributeMaxDynamicSharedMemorySize, SC_SMEM);
    cudaFuncSetAttribute(outconv_tc_kernel,
                         cudaFuncAttributeMaxDynamicSharedMemorySize, PJ_SMEM);

    dim3 blk(256);
    proj_tc_kernel<<<dim3(RR / 128, CC / 128, 2), blk, PJ_SMEM>>>(x, Wq, bq, Wk, bk);
    scores_mma_kernel<<<dim3(RR / 128, BB), blk, SC_SMEM>>>();
    softmax_kernel<<<BB, blk>>>();
    outconv_tc_kernel<<<dim3(CC / 128, HWD / 128, BB), blk, PJ_SMEM>>>(x, W6, b6, out);
}

// round 7
// speedup vs baseline: 1.2008x; 1.1140x over previous
#include <cuda_runtime.h>
#include <cuda_bf16.h>
#include <cstdint>

#define BB  8
#define CC  512
#define HWD 1024
#define RR  8192   // BB*HWD

// Scratch (device globals — no runtime allocation allowed)
__device__ __nv_bfloat16 g_q[RR * CC];   // bf16 projections (8 MB each)
__device__ __nv_bfloat16 g_k[RR * CC];
__device__ float g_pmax[RR * BB];        // per-query, per-image max score
__device__ float g_w[BB * HWD];          // softmax gate weights

// ============================================================================
// Helpers
// ============================================================================
__device__ __forceinline__ uint32_t smem_u32(const void* p) {
    uint32_t a;
    asm("{ .reg .u64 t; cvta.to.shared.u64 t, %1; cvt.u32.u64 %0, t; }"
        : "=r"(a) : "l"(p));
    return a;
}
__device__ __forceinline__ void cp_cg16(uint32_t s, const void* g) {
    asm volatile("cp.async.cg.shared.global [%0], [%1], 16;" :: "r"(s), "l"(g));
}
__device__ __forceinline__ void cp_commit() {
    asm volatile("cp.async.commit_group;" ::: "memory");
}
template <int N> __device__ __forceinline__ void cp_wait() {
    asm volatile("cp.async.wait_group %0;" :: "n"(N) : "memory");
}
__device__ __forceinline__ void mma_tf32_16n8k8(
    float* c, uint32_t a0, uint32_t a1, uint32_t a2, uint32_t a3,
    uint32_t b0, uint32_t b1)
{
    asm volatile(
        "mma.sync.aligned.m16n8k8.row.col.f32.tf32.tf32.f32 "
        "{%0,%1,%2,%3}, {%4,%5,%6,%7}, {%8,%9}, {%0,%1,%2,%3};"
        : "+f"(c[0]), "+f"(c[1]), "+f"(c[2]), "+f"(c[3])
        : "r"(a0), "r"(a1), "r"(a2), "r"(a3), "r"(b0), "r"(b1));
}
__device__ __forceinline__ void mma_bf16_16n8k16(
    float* c, const uint32_t* a, uint32_t b0, uint32_t b1)
{
    asm volatile(
        "mma.sync.aligned.m16n8k16.row.col.f32.bf16.bf16.f32 "
        "{%0,%1,%2,%3}, {%4,%5,%6,%7}, {%8,%9}, {%0,%1,%2,%3};"
        : "+f"(c[0]), "+f"(c[1]), "+f"(c[2]), "+f"(c[3])
        : "r"(a[0]), "r"(a[1]), "r"(a[2]), "r"(a[3]), "r"(b0), "r"(b1));
}
__device__ __forceinline__ void ldm_x4(uint32_t* r, uint32_t addr) {
    asm volatile("ldmatrix.sync.aligned.m8n8.x4.shared.b16 {%0,%1,%2,%3}, [%4];"
        : "=r"(r[0]), "=r"(r[1]), "=r"(r[2]), "=r"(r[3]) : "r"(addr));
}
__device__ __forceinline__ void tf32_split(float v, uint32_t& hi, uint32_t& lo) {
    uint32_t hb = __float_as_uint(v) & 0xFFFFE000u;
    hi = hb;
    lo = __float_as_uint(v - __uint_as_float(hb));
}

// Shared tiling constants (all GEMM kernels: 256 threads, 8 warps)
#define SBK  32      // K-chunk
#define PADR 36      // fp32 [rows][k] pad (proj/outconv)
#define PADK 136     // fp32 [k][cols] pad

// ============================================================================
// Kernel 1: q/k projection on tf32 mma.sync. grid (64, 4, 2). 2 CTAs/SM.
//   Epilogue converts to bf16 and stores to g_q/g_k.
// ============================================================================
#define PJ_A_F (SBK * PADK)          // 4352 floats / stage
#define PJ_B_F (128 * PADR)          // 4608 floats / stage
#define PJ_SMEM (3 * (PJ_A_F + PJ_B_F) * 4)

__global__ __launch_bounds__(256, 2) void proj_tc_kernel(
    const float* __restrict__ x,
    const float* __restrict__ Wq, const float* __restrict__ bq,
    const float* __restrict__ Wk, const float* __restrict__ bk)
{
    extern __shared__ float sm[];
    const uint32_t sbase = smem_u32(sm);

    const int dst = blockIdx.z;
    const float* W    = dst ? Wk : Wq;
    const float* bias = dst ? bk : bq;
    __nv_bfloat16* out = dst ? g_k : g_q;

    const int t    = threadIdx.x;
    const int lane = t & 31;
    const int wid  = t >> 5;
    const int wm   = wid >> 2;
    const int wn   = wid & 3;
    const int gid  = lane >> 2;
    const int tig  = lane & 3;

    const int r0  = blockIdx.x * 128;
    const int co0 = blockIdx.y * 128;
    const int b   = r0 / HWD;
    const int p0  = r0 % HWD;
    const float* xb = x + (size_t)b * CC * HWD;

    auto issue = [&](int c) {
        const int s  = c % 3;
        const int k0 = c * SBK;
        uint32_t As = sbase + (uint32_t)(s * PJ_A_F) * 4;
        #pragma unroll
        for (int u = 0; u < 4; u++) {
            int f = t + u * 256, kk = f >> 5, p4 = (f & 31) * 4;
            cp_cg16(As + (uint32_t)(kk * PADK + p4) * 4,
                    xb + (size_t)(k0 + kk) * HWD + p0 + p4);
        }
        uint32_t Bs = sbase + (uint32_t)(3 * PJ_A_F + s * PJ_B_F) * 4;
        #pragma unroll
        for (int u = 0; u < 4; u++) {
            int f = t + u * 256, n = f >> 3, c4 = (f & 7) * 4;
            cp_cg16(Bs + (uint32_t)(n * PADR + c4) * 4,
                    W + (size_t)(co0 + n) * CC + k0 + c4);
        }
        cp_commit();
    };

    float acc[4][4][4];
    #pragma unroll
    for (int mt = 0; mt < 4; mt++)
        #pragma unroll
        for (int nt = 0; nt < 4; nt++)
            #pragma unroll
            for (int v = 0; v < 4; v++) acc[mt][nt][v] = 0.f;

    issue(0); issue(1);
    for (int c = 0; c < 16; ++c) {
        if (c < 15) cp_wait<1>(); else cp_wait<0>();
        __syncthreads();
        if (c + 2 < 16) issue(c + 2);

        const float* Ab = sm + (c % 3) * PJ_A_F;                 // [k][p]
        const float* Bb = sm + 3 * PJ_A_F + (c % 3) * PJ_B_F;    // [co][k]

        #pragma unroll
        for (int ks = 0; ks < 4; ++ks) {
            const int col = ks * 8 + tig;
            uint32_t a[4][4];
            #pragma unroll
            for (int mt = 0; mt < 4; ++mt) {
                int r = wm * 64 + mt * 16 + gid;
                a[mt][0] = __float_as_uint(Ab[col * PADK + r]);
                a[mt][1] = __float_as_uint(Ab[col * PADK + r + 8]);
                a[mt][2] = __float_as_uint(Ab[(col + 4) * PADK + r]);
                a[mt][3] = __float_as_uint(Ab[(col + 4) * PADK + r + 8]);
            }
            #pragma unroll
            for (int nt = 0; nt < 4; ++nt) {
                int n = wn * 32 + nt * 8 + gid;
                uint32_t b0 = __float_as_uint(Bb[n * PADR + col]);
                uint32_t b1 = __float_as_uint(Bb[n * PADR + col + 4]);
                #pragma unroll
                for (int mt = 0; mt < 4; ++mt)
                    mma_tf32_16n8k8(acc[mt][nt],
                                    a[mt][0], a[mt][1], a[mt][2], a[mt][3],
                                    b0, b1);
            }
        }
    }

    #pragma unroll
    for (int mt = 0; mt < 4; ++mt) {
        int row = r0 + wm * 64 + mt * 16 + gid;
        #pragma unroll
        for (int nt = 0; nt < 4; ++nt) {
            int co = co0 + wn * 32 + nt * 8 + tig * 2;
            float bs0 = bias[co], bs1 = bias[co + 1];
            __nv_bfloat162 v0, v1;
            v0.x = __float2bfloat16(acc[mt][nt][0] + bs0);
            v0.y = __float2bfloat16(acc[mt][nt][1] + bs1);
            v1.x = __float2bfloat16(acc[mt][nt][2] + bs0);
            v1.y = __float2bfloat16(acc[mt][nt][3] + bs1);
            *(__nv_bfloat162*)&out[(size_t)row * CC + co]       = v0;
            *(__nv_bfloat162*)&out[(size_t)(row + 8) * CC + co] = v1;
        }
    }
}

// ============================================================================
// Kernel 2: fused scores + per-image max via bf16 mma (m16n8k16) + ldmatrix.
//   grid (64, 8). Block: 128 queries x 1024 keys (one image), N-tile = 128
//   (8 N-tiles x 16 K-chunks = 128 chunks), 3-stage cp.async ring.
//   80B row pitch -> conflict-free ldmatrix/STS. 2 CTAs/SM.
// ============================================================================
#define PB 40                         // bf16 elems per smem row (32 + 8 pad)
#define SC_TILE_B (128 * PB * 2)      // 10240 bytes (A or B tile)
#define SC_STAGE_B (2 * SC_TILE_B)    // 20480
#define SC_RED_OFF (3 * SC_STAGE_B)   // 61440
#define SC_SMEM (SC_RED_OFF + 512 * 4)

__global__ __launch_bounds__(256, 2) void scores_mma_kernel()
{
    extern __shared__ char smc[];
    const uint32_t sbase = smem_u32(smc);

    const int t    = threadIdx.x;
    const int lane = t & 31;
    const int wid  = t >> 5;
    const int wm   = wid >> 2;
    const int wn   = wid & 3;
    const int gid  = lane >> 2;
    const int tig  = lane & 3;
    const int q0   = blockIdx.x * 128;
    const size_t kb = (size_t)blockIdx.y * HWD;

    float* red = (float*)(smc + SC_RED_OFF);
    float qm = -1e30f;
    const __nv_bfloat16* qp = g_q + (size_t)q0 * CC;

    // ldmatrix lane address components
    const int lrow = lane & 15;
    const int lseg = (lane >> 4) * 8;

    auto issue = [&](int g) {
        const int s   = g % 3;
        const int ntl = g >> 4;
        const int k0  = (g & 15) * SBK;
        uint32_t As = sbase + (uint32_t)(s * SC_STAGE_B);
        #pragma unroll
        for (int u = 0; u < 2; u++) {
            int f = t + u * 256, r = f & 127, seg = f >> 7;   // conflict-free STS
            cp_cg16(As + (uint32_t)(r * PB + seg * 8) * 2,
                    qp + (size_t)r * CC + k0 + seg * 8);
        }
        uint32_t Bs = As + SC_TILE_B;
        const __nv_bfloat16* kp = g_k + (kb + (size_t)ntl * 128) * CC;
        #pragma unroll
        for (int u = 0; u < 2; u++) {
            int f = t + u * 256, r = f & 127, seg = f >> 7;
            cp_cg16(Bs + (uint32_t)(r * PB + seg * 8) * 2,
                    kp + (size_t)r * CC + k0 + seg * 8);
        }
        cp_commit();
    };

    float acc[4][4][4];

    issue(0); issue(1);
    for (int g = 0; g < 128; ++g) {
        if ((g & 15) == 0) {
            #pragma unroll
            for (int mt = 0; mt < 4; mt++)
                #pragma unroll
                for (int nt = 0; nt < 4; nt++)
                    #pragma unroll
                    for (int v = 0; v < 4; v++) acc[mt][nt][v] = 0.f;
        }
        if (g < 127) cp_wait<1>(); else cp_wait<0>();
        __syncthreads();
        if (g + 2 < 128) issue(g + 2);

        const uint32_t Ab = sbase + (uint32_t)((g % 3) * SC_STAGE_B);
        const uint32_t Bb = Ab + SC_TILE_B;

        #pragma unroll
        for (int ks = 0; ks < 2; ++ks) {
            const int kcol = ks * 16 + lseg;
            uint32_t a[4][4];
            #pragma unroll
            for (int mt = 0; mt < 4; ++mt)
                ldm_x4(a[mt], Ab + (uint32_t)((wm * 64 + mt * 16 + lrow) * PB + kcol) * 2);
            uint32_t bf[2][4];
            #pragma unroll
            for (int nh = 0; nh < 2; ++nh)
                ldm_x4(bf[nh], Bb + (uint32_t)((wn * 32 + nh * 16 + lrow) * PB + kcol) * 2);
            #pragma unroll
            for (int nt = 0; nt < 4; ++nt) {
                uint32_t b0 = bf[nt >> 1][nt & 1];
                uint32_t b1 = bf[nt >> 1][(nt & 1) + 2];
                #pragma unroll
                for (int mt = 0; mt < 4; ++mt)
                    mma_bf16_16n8k16(acc[mt][nt], a[mt], b0, b1);
            }
        }

        if ((g & 15) == 15) {
            #pragma unroll
            for (int mt = 0; mt < 4; ++mt) {
                float m0 = -1e30f, m1 = -1e30f;
                #pragma unroll
                for (int nt = 0; nt < 4; ++nt) {
                    m0 = fmaxf(m0, fmaxf(acc[mt][nt][0], acc[mt][nt][1]));
                    m1 = fmaxf(m1, fmaxf(acc[mt][nt][2], acc[mt][nt][3]));
                }
                m0 = fmaxf(m0, __shfl_xor_sync(0xffffffffu, m0, 1));
                m0 = fmaxf(m0, __shfl_xor_sync(0xffffffffu, m0, 2));
                m1 = fmaxf(m1, __shfl_xor_sync(0xffffffffu, m1, 1));
                m1 = fmaxf(m1, __shfl_xor_sync(0xffffffffu, m1, 2));
                if (tig == 0) {
                    int r = wm * 64 + mt * 16 + gid;
                    red[wn * 128 + r]     = m0;
                    red[wn * 128 + r + 8] = m1;
                }
            }
            __syncthreads();
            if (t < 128) {
                float v = fmaxf(fmaxf(red[t], red[128 + t]),
                                fmaxf(red[256 + t], red[384 + t]));
                qm = fmaxf(qm, v);
            }
            __syncthreads();
        }
    }

    if (t < 128)
        g_pmax[(size_t)(q0 + t) * BB + blockIdx.y] = qm;
}

// ============================================================================
// Kernel 3: logits = mean-over-images(pmax) / sqrt(C); softmax per batch.
// ============================================================================
__global__ __launch_bounds__(256) void softmax_kernel()
{
    const int b = blockIdx.x;
    const int t = threadIdx.x;
    __shared__ float smr[256];
    __shared__ float logits[HWD];
    const float scale = 1.0f / sqrtf((float)CC);

    float lmax = -1e30f;
    for (int p = t; p < HWD; p += 256) {
        float s = 0.f;
        #pragma unroll
        for (int img = 0; img < BB; img++)
            s += g_pmax[(size_t)(b * HWD + p) * BB + img];
        float lg = s * (1.0f / BB) * scale;
        logits[p] = lg;
        lmax = fmaxf(lmax, lg);
    }
    smr[t] = lmax; __syncthreads();
    for (int s = 128; s > 0; s >>= 1) {
        if (t < s) smr[t] = fmaxf(smr[t], smr[t + s]);
        __syncthreads();
    }
    float gmax = smr[0]; __syncthreads();

    float lsum = 0.f;
    for (int p = t; p < HWD; p += 256) {
        float e = expf(logits[p] - gmax);
        logits[p] = e;
        lsum += e;
    }
    smr[t] = lsum; __syncthreads();
    for (int s = 128; s > 0; s >>= 1) {
        if (t < s) smr[t] += smr[t + s];
        __syncthreads();
    }
    float inv = 1.0f / smr[0];
    for (int p = t; p < HWD; p += 256)
        g_w[b * HWD + p] = logits[p] * inv;
}

// ============================================================================
// Kernel 4: gated output conv on 3xTF32 split mma. grid (4, 8, 8). 2 CTAs/SM.
// ============================================================================
__global__ __launch_bounds__(256, 2) void outconv_tc_kernel(
    const float* __restrict__ x, const float* __restrict__ W6,
    const float* __restrict__ b6, float* __restrict__ out)
{
    extern __shared__ float sm[];
    const uint32_t sbase = smem_u32(sm);

    const int t    = threadIdx.x;
    const int lane = t & 31;
    const int wid  = t >> 5;
    const int wm   = wid >> 2;
    const int wn   = wid & 3;
    const int gid  = lane >> 2;
    const int tig  = lane & 3;

    const int co0 = blockIdx.x * 128;
    const int p0  = blockIdx.y * 128;
    const int b   = blockIdx.z;
    const float* xb = x + (size_t)b * CC * HWD;

    auto issue = [&](int c) {
        const int s  = c % 3;
        const int k0 = c * SBK;
        uint32_t As = sbase + (uint32_t)(s * PJ_B_F) * 4;      // [co][k] PADR
        #pragma unroll
        for (int u = 0; u < 4; u++) {
            int f = t + u * 256, m = f >> 3, c4 = (f & 7) * 4;
            cp_cg16(As + (uint32_t)(m * PADR + c4) * 4,
                    W6 + (size_t)(co0 + m) * CC + k0 + c4);
        }
        uint32_t Bs = sbase + (uint32_t)(3 * PJ_B_F + s * PJ_A_F) * 4;  // [k][p] PADK
        #pragma unroll
        for (int u = 0; u < 4; u++) {
            int f = t + u * 256, kk = f >> 5, p4 = (f & 31) * 4;
            cp_cg16(Bs + (uint32_t)(kk * PADK + p4) * 4,
                    xb + (size_t)(k0 + kk) * HWD + p0 + p4);
        }
        cp_commit();
    };

    float acc[4][4][4];
    #pragma unroll
    for (int mt = 0; mt < 4; mt++)
        #pragma unroll
        for (int nt = 0; nt < 4; nt++)
            #pragma unroll
            for (int v = 0; v < 4; v++) acc[mt][nt][v] = 0.f;

    issue(0); issue(1);
    for (int c = 0; c < 16; ++c) {
        if (c < 15) cp_wait<1>(); else cp_wait<0>();
        __syncthreads();
        if (c + 2 < 16) issue(c + 2);

        const float* Ab = sm + (c % 3) * PJ_B_F;                 // [co][k]
        const float* Bb = sm + 3 * PJ_B_F + (c % 3) * PJ_A_F;    // [k][p]

        #pragma unroll
        for (int ks = 0; ks < 4; ++ks) {
            const int col = ks * 8 + tig;
            uint32_t ah[4][4], al[4][4];
            #pragma unroll
            for (int mt = 0; mt < 4; ++mt) {
                int m = wm * 64 + mt * 16 + gid;
                tf32_split(Ab[m * PADR + col],           ah[mt][0], al[mt][0]);
                tf32_split(Ab[(m + 8) * PADR + col],     ah[mt][1], al[mt][1]);
                tf32_split(Ab[m * PADR + col + 4],       ah[mt][2], al[mt][2]);
                tf32_split(Ab[(m + 8) * PADR + col + 4], ah[mt][3], al[mt][3]);
            }
            #pragma unroll
            for (int nt = 0; nt < 4; ++nt) {
                int n = wn * 32 + nt * 8 + gid;
                uint32_t bh0, bl0, bh1, bl1;
                tf32_split(Bb[col * PADK + n],       bh0, bl0);
                tf32_split(Bb[(col + 4) * PADK + n], bh1, bl1);
                #pragma unroll
                for (int mt = 0; mt < 4; ++mt) {
                    mma_tf32_16n8k8(acc[mt][nt],
                                    ah[mt][0], ah[mt][1], ah[mt][2], ah[mt][3],
                                    bh0, bh1);
                    mma_tf32_16n8k8(acc[mt][nt],
                                    ah[mt][0], ah[mt][1], ah[mt][2], ah[mt][3],
                                    bl0, bl1);
                    mma_tf32_16n8k8(acc[mt][nt],
                                    al[mt][0], al[mt][1], al[mt][2], al[mt][3],
                                    bh0, bh1);
                }
            }
        }
    }

    #pragma unroll
    for (int mt = 0; mt < 4; ++mt) {
        int co = co0 + wm * 64 + mt * 16 + gid;
        float bs0 = b6[co], bs1 = b6[co + 8];
        #pragma unroll
        for (int nt = 0; nt < 4; ++nt) {
            int p = p0 + wn * 32 + nt * 8 + tig * 2;
            float g0 = g_w[b * HWD + p];
            float g1 = g_w[b * HWD + p + 1];
            float2 o0 = { acc[mt][nt][0] * g0 + bs0, acc[mt][nt][1] * g1 + bs0 };
            float2 o1 = { acc[mt][nt][2] * g0 + bs1, acc[mt][nt][3] * g1 + bs1 };
            *(float2*)&out[((size_t)(b * CC + co)) * HWD + p]     = o0;
            *(float2*)&out[((size_t)(b * CC + co + 8)) * HWD + p] = o1;
        }
    }
}

// ============================================================================
extern "C" void kernel_launch(void* const* d_in, const int* in_sizes, int n_in,
                              void* d_out, int out_size)
{
    const float* x  = (const float*)d_in[0];
    const float* Wq = (const float*)d_in[1];
    const float* bq = (const float*)d_in[2];
    const float* Wk = (const float*)d_in[3];
    const float* bk = (const float*)d_in[4];
    const float* W6 = (const float*)d_in[5];
    const float* b6 = (const float*)d_in[6];
    float* out = (float*)d_out;

    cudaFuncSetAttribute(proj_tc_kernel,
                         cudaFuncAttributeMaxDynamicSharedMemorySize, PJ_SMEM);
    cudaFuncSetAttribute(scores_mma_kernel,
                         cudaFuncAttributeMaxDynamicSharedMemorySize, SC_SMEM);
    cudaFuncSetAttribute(outconv_tc_kernel,
                         cudaFuncAttributeMaxDynamicSharedMemorySize, PJ_SMEM);

    dim3 blk(256);
    proj_tc_kernel<<<dim3(RR / 128, CC / 128, 2), blk, PJ_SMEM>>>(x, Wq, bq, Wk, bk);
    scores_mma_kernel<<<dim3(RR / 128, BB), blk, SC_SMEM>>>();
    softmax_kernel<<<BB, blk>>>();
    outconv_tc_kernel<<<dim3(CC / 128, HWD / 128, BB), blk, PJ_SMEM>>>(x, W6, b6, out);
}